// round 13
// baseline (speedup 1.0000x reference)
#include <cuda_runtime.h>
#include <cuda_fp16.h>
#include <cstdint>

#define D 128
#define MAXN 50000
#define NPAD 50176                 // padded rows so GEMM tail loads stay in-bounds
#define MAXE 800000
#define SCAN_BLK 512
#define SCAN_GRID ((MAXN + SCAN_BLK - 1) / SCAN_BLK)   // 98

// Scratch (device globals — no runtime allocation allowed)
__device__ __half g_x16[(size_t)NPAD * D];   // fp16 x (gather + GEMM A)
__device__ __half g_h16[(size_t)NPAD * D];   // fp16 h (gather + GEMM A)
__device__ __half g_w16[2 * 128 * 256];      // fp16 W [layer][n][k] (k<128=Wl, else Wr)
__device__ int    g_deg[MAXN];               // -> exclusive prefix within scan block
__device__ int    g_part[SCAN_GRID];         // -> exclusive block offsets
__device__ int    g_cursor[MAXN];
__device__ int    g_perm[MAXE];
__device__ int    g_done;                    // scan completion counter (self-resetting)
__device__ int    g_idx64;

// ---------------------------------------------------------------------------
__device__ __forceinline__ uint32_t smem_u32(const void* p) {
    uint32_t a;
    asm("{ .reg .u64 t; cvta.to.shared.u64 t, %1; cvt.u32.u64 %0, t; }"
        : "=r"(a) : "l"(p));
    return a;
}
__device__ __forceinline__ void ldsm_x4(uint32_t& r0, uint32_t& r1,
                                        uint32_t& r2, uint32_t& r3, uint32_t addr) {
    asm volatile("ldmatrix.sync.aligned.m8n8.x4.shared.b16 {%0,%1,%2,%3}, [%4];"
                 : "=r"(r0), "=r"(r1), "=r"(r2), "=r"(r3) : "r"(addr));
}
__device__ __forceinline__ void mma_fp16(float* c, const uint32_t* a, const uint32_t* b) {
    asm volatile(
        "mma.sync.aligned.m16n8k16.row.col.f32.f16.f16.f32 "
        "{%0,%1,%2,%3}, {%4,%5,%6,%7}, {%8,%9}, {%0,%1,%2,%3};"
        : "+f"(c[0]), "+f"(c[1]), "+f"(c[2]), "+f"(c[3])
        : "r"(a[0]), "r"(a[1]), "r"(a[2]), "r"(a[3]), "r"(b[0]), "r"(b[1]));
}

__device__ __forceinline__ int clampN(long long v, int N) {
    if (v < 0) v = 0;
    if (v >= N) v = N - 1;
    return (int)v;
}

// ---------------------------------------------------------------------------
// Merged prep: zero deg/cursor + dtype detection + x->fp16 + W->fp16
// ---------------------------------------------------------------------------
__global__ void prep_kernel(const long long* __restrict__ e,
                            const float* __restrict__ x,
                            const float* __restrict__ Wl0, const float* __restrict__ Wr0,
                            const float* __restrict__ Wl1, const float* __restrict__ Wr1,
                            int E, int N, int n4) {
    int i = blockIdx.x * blockDim.x + threadIdx.x;

    if (i < N) { g_deg[i] = 0; g_cursor[i] = 0; }

    if (i < n4) {
        float4 v = reinterpret_cast<const float4*>(x)[i];
        __half2 p0 = __floats2half2_rn(v.x, v.y);
        __half2 p1 = __floats2half2_rn(v.z, v.w);
        uint2 pk;
        pk.x = *reinterpret_cast<uint32_t*>(&p0);
        pk.y = *reinterpret_cast<uint32_t*>(&p1);
        reinterpret_cast<uint2*>(g_x16)[i] = pk;
    }

    if (i < 2 * 128 * 256) {
        int layer = i >> 15;
        int rem   = i & 32767;
        int n     = rem >> 8;
        int k     = rem & 255;
        const float* W = layer ? (k < 128 ? Wl1 : Wr1) : (k < 128 ? Wl0 : Wr0);
        g_w16[i] = __float2half_rn(W[n * 128 + (k & 127)]);
    }

    if (blockIdx.x == 0) {
        __shared__ int bad;
        if (threadIdx.x == 0) bad = 0;
        __syncthreads();
        int limit = 1024 < 2 * E ? 1024 : 2 * E;
        for (int k = threadIdx.x; k < limit; k += blockDim.x) {
            long long v = e[k];
            if (v < 0 || v >= (long long)N) bad = 1;
        }
        __syncthreads();
        if (threadIdx.x == 0) g_idx64 = bad ? 0 : 1;
    }
}

// ---------------------------------------------------------------------------
// CSR build
// ---------------------------------------------------------------------------
__global__ void count_kernel(const void* __restrict__ eidx, int E, int N) {
    int t = blockIdx.x * blockDim.x + threadIdx.x;
    int e0 = t * 4;
    if (e0 >= E) return;
    int m = E - e0;
    int d[4];
    if (g_idx64) {
        const long long* ei = (const long long*)eidx + E;
#pragma unroll
        for (int j = 0; j < 4; j++) d[j] = clampN(ei[(j < m) ? e0 + j : e0], N);
    } else {
        const int* ei = (const int*)eidx + E;
        if (m >= 4) {
            int4 p = *reinterpret_cast<const int4*>(ei + e0);
            d[0] = clampN(p.x, N); d[1] = clampN(p.y, N);
            d[2] = clampN(p.z, N); d[3] = clampN(p.w, N);
        } else {
#pragma unroll
            for (int j = 0; j < 4; j++) d[j] = clampN(ei[(j < m) ? e0 + j : e0], N);
        }
    }
#pragma unroll
    for (int j = 0; j < 4; j++)
        if (j < m) atomicAdd(&g_deg[d[j]], 1);
}

// Merged scan: per-block exclusive scan of deg; last-finishing block scans the
// block partials. rowptr[i] computed by consumers as deg[i] + part[i>>9].
__global__ void scan_kernel(int N) {
    __shared__ int sh[SCAN_BLK];
    __shared__ int isLast;
    int t = threadIdx.x;
    int i = blockIdx.x * SCAN_BLK + t;
    int v = (i < N) ? g_deg[i] : 0;
    sh[t] = v;
    __syncthreads();
#pragma unroll
    for (int ofs = 1; ofs < SCAN_BLK; ofs <<= 1) {
        int add = (t >= ofs) ? sh[t - ofs] : 0;
        __syncthreads();
        sh[t] += add;
        __syncthreads();
    }
    if (i < N) g_deg[i] = sh[t] - v;          // exclusive within block
    if (t == SCAN_BLK - 1) g_part[blockIdx.x] = sh[t];

    __threadfence();
    if (t == 0) isLast = (atomicAdd(&g_done, 1) == (int)gridDim.x - 1);
    __syncthreads();
    if (isLast) {
        int nb = gridDim.x;
        int pv = (t < nb) ? g_part[t] : 0;
        sh[t] = pv;
        __syncthreads();
#pragma unroll
        for (int ofs = 1; ofs < SCAN_BLK; ofs <<= 1) {
            int add = (t >= ofs) ? sh[t - ofs] : 0;
            __syncthreads();
            sh[t] += add;
            __syncthreads();
        }
        if (t < nb) g_part[t] = sh[t] - pv;   // exclusive block offsets
        if (t == 0) g_done = 0;               // reset for next graph replay
    }
}

__global__ void fill_kernel(const void* __restrict__ eidx, int E, int N) {
    int t = blockIdx.x * blockDim.x + threadIdx.x;
    int e0 = t * 4;
    if (e0 >= E) return;
    int m = E - e0;
    int s[4], d[4];
    if (g_idx64) {
        const long long* es = (const long long*)eidx;
        const long long* ed = es + E;
#pragma unroll
        for (int j = 0; j < 4; j++) {
            int e = (j < m) ? e0 + j : e0;
            s[j] = clampN(es[e], N);
            d[j] = clampN(ed[e], N);
        }
    } else {
        const int* es = (const int*)eidx;
        const int* ed = es + E;
        if (m >= 4) {
            int4 ps = *reinterpret_cast<const int4*>(es + e0);
            int4 pd = *reinterpret_cast<const int4*>(ed + e0);
            s[0] = clampN(ps.x, N); s[1] = clampN(ps.y, N);
            s[2] = clampN(ps.z, N); s[3] = clampN(ps.w, N);
            d[0] = clampN(pd.x, N); d[1] = clampN(pd.y, N);
            d[2] = clampN(pd.z, N); d[3] = clampN(pd.w, N);
        } else {
#pragma unroll
            for (int j = 0; j < 4; j++) {
                int e = (j < m) ? e0 + j : e0;
                s[j] = clampN(es[e], N);
                d[j] = clampN(ed[e], N);
            }
        }
    }
#pragma unroll
    for (int j = 0; j < 4; j++)
        if (j < m) {
            int dj = d[j];
            int base = g_deg[dj] + g_part[dj >> 9];        // rowptr[dj]
            int pos = base + atomicAdd(&g_cursor[dj], 1);
            g_perm[pos] = s[j];
        }
}

// ---------------------------------------------------------------------------
// Fused agg + GEMM per layer.
// Phase 1: each CTA aggregates its 128 rows (warp per node, fp32 accumulate,
//          fp16 mean) directly into smem A-tiles SA0 (k 0..63) / SA1 (k 64..127).
// Phase 2: fp16 single-pass GEMM  out = [agg | x/h] @ W^T + bias (+ReLU).
// ---------------------------------------------------------------------------
#define ROWB 144
#define TILE_BYTES (128 * ROWB)
#define SA0   0
#define SA1   TILE_BYTES
#define SAX   (2 * TILE_BYTES)
#define SB    (3 * TILE_BYTES)
#define SMEM_TOTAL (4 * TILE_BYTES)   // 73728

__global__ void __launch_bounds__(256, 2)
sage_fused(const float* __restrict__ bias,
           float* __restrict__ outp,
           int N, int E, int layer) {
    extern __shared__ __align__(128) char smem[];
    uint32_t sb = smem_u32(smem);

    int tid = threadIdx.x, wid = tid >> 5, lane = tid & 31;
    int warpM = wid & 3, warpN = wid >> 2;
    int row0 = blockIdx.x * 128;
    int relu = (layer == 0);

    const __half* __restrict__ X = layer ? g_h16 : g_x16;

    // ---------------- Phase 1: aggregate this CTA's 128 rows ----------------
    {
        // smem store target for lane: cols [4*lane, 4*lane+4)
        int col = lane * 4;
        int sm_off = (col < 64 ? SA0 : SA1);
        int cc = col & 63;
        for (int i = 0; i < 16; i++) {
            int r = wid * 16 + i;          // local row 0..127
            int nd = row0 + r;
            float a0 = 0.f, a1 = 0.f, a2 = 0.f, a3 = 0.f;
            float inv = 0.f;
            if (nd < N) {
                int beg = g_deg[nd] + g_part[nd >> 9];
                int end = (nd + 1 < N) ? (g_deg[nd + 1] + g_part[(nd + 1) >> 9]) : E;
                for (int base = beg; base < end; base += 32) {
                    int idx = base + lane;
                    int sv = (idx < end) ? g_perm[idx] : 0;
                    int m = min(32, end - base);
                    for (int j = 0; j < m; j++) {
                        int s = __shfl_sync(0xffffffffu, sv, j);
                        uint2 pk = reinterpret_cast<const uint2*>(X + (size_t)s * D)[lane];
                        __half2 h0 = *reinterpret_cast<__half2*>(&pk.x);
                        __half2 h1 = *reinterpret_cast<__half2*>(&pk.y);
                        float2 f0 = __half22float2(h0);
                        float2 f1 = __half22float2(h1);
                        a0 += f0.x; a1 += f0.y; a2 += f1.x; a3 += f1.y;
                    }
                }
                inv = (end > beg) ? 1.0f / (float)(end - beg) : 0.f;
            }
            __half2 p0 = __floats2half2_rn(a0 * inv, a1 * inv);
            __half2 p1 = __floats2half2_rn(a2 * inv, a3 * inv);
            uint2 pk;
            pk.x = *reinterpret_cast<uint32_t*>(&p0);
            pk.y = *reinterpret_cast<uint32_t*>(&p1);
            *reinterpret_cast<uint2*>(smem + sm_off + r * ROWB + cc * 2) = pk;
        }
    }
    __syncthreads();

    // ---------------- Phase 2: GEMM ----------------
    uint32_t aoff[2], boff[4];
#pragma unroll
    for (int mi = 0; mi < 2; mi++)
        aoff[mi] = (uint32_t)((warpM * 32 + mi * 16 + (lane & 15)) * ROWB + (lane >> 4) * 16);
#pragma unroll
    for (int np = 0; np < 4; np++)
        boff[np] = (uint32_t)((warpN * 64 + np * 16 + (lane & 7) + ((lane & 16) ? 8 : 0)) * ROWB
                              + ((lane >> 3) & 1) * 16);

    float acc[2][8][4];
#pragma unroll
    for (int mi = 0; mi < 2; mi++)
#pragma unroll
        for (int ni = 0; ni < 8; ni++)
#pragma unroll
            for (int j = 0; j < 4; j++) acc[mi][ni][j] = 0.f;

    for (int c = 0; c < 4; c++) {
        const int kb = (c & 1) * 64;
        if (c > 0) __syncthreads();   // SB (and SAX) reuse protection

        // load B chunk; for c>=2 also load A chunk from global x/h
#pragma unroll
        for (int i = 0; i < 4; i++) {
            int f = i * 256 + tid;    // uint4 index 0..1023
            int r = f >> 3;           // row 0..127
            int c8 = (f & 7) * 8;     // fp16 col offset 0..56
            int sm = r * ROWB + c8 * 2;

            size_t gb = ((size_t)layer * 128 + r) * 256 + c * 64 + c8;
            *reinterpret_cast<uint4*>(smem + SB + sm) =
                *reinterpret_cast<const uint4*>(g_w16 + gb);

            if (c >= 2)
                *reinterpret_cast<uint4*>(smem + SAX + sm) =
                    *reinterpret_cast<const uint4*>(X + (size_t)(row0 + r) * D + kb + c8);
        }
        __syncthreads();

        uint32_t abase = sb + ((c == 0) ? SA0 : (c == 1) ? SA1 : SAX);
#pragma unroll
        for (int ks = 0; ks < 4; ks++) {
            uint32_t kbyte = (uint32_t)(ks * 32);
            uint32_t a[2][4], b[8][2];
#pragma unroll
            for (int mi = 0; mi < 2; mi++)
                ldsm_x4(a[mi][0], a[mi][1], a[mi][2], a[mi][3],
                        abase + aoff[mi] + kbyte);
#pragma unroll
            for (int np = 0; np < 4; np++)
                ldsm_x4(b[2 * np][0], b[2 * np][1], b[2 * np + 1][0], b[2 * np + 1][1],
                        sb + SB + boff[np] + kbyte);
#pragma unroll
            for (int mi = 0; mi < 2; mi++)
#pragma unroll
                for (int ni = 0; ni < 8; ni++)
                    mma_fp16(acc[mi][ni], a[mi], b[ni]);
        }
    }

    int g = lane >> 2, t = lane & 3;
#pragma unroll
    for (int mi = 0; mi < 2; mi++) {
        int r1 = row0 + warpM * 32 + mi * 16 + g;
        int r2 = r1 + 8;
#pragma unroll
        for (int ni = 0; ni < 8; ni++) {
            int col = warpN * 64 + ni * 8 + t * 2;
            float2 bs = *reinterpret_cast<const float2*>(bias + col);
            float2 o1, o2;
            o1.x = acc[mi][ni][0] + bs.x; o1.y = acc[mi][ni][1] + bs.y;
            o2.x = acc[mi][ni][2] + bs.x; o2.y = acc[mi][ni][3] + bs.y;
            if (relu) {
                o1.x = fmaxf(o1.x, 0.f); o1.y = fmaxf(o1.y, 0.f);
                o2.x = fmaxf(o2.x, 0.f); o2.y = fmaxf(o2.y, 0.f);
            }
            if (layer == 0) {
                if (r1 < N) {
                    __half2 p = __floats2half2_rn(o1.x, o1.y);
                    *reinterpret_cast<__half2*>(g_h16 + (size_t)r1 * D + col) = p;
                }
                if (r2 < N) {
                    __half2 p = __floats2half2_rn(o2.x, o2.y);
                    *reinterpret_cast<__half2*>(g_h16 + (size_t)r2 * D + col) = p;
                }
            } else {
                if (r1 < N) *reinterpret_cast<float2*>(outp + (size_t)r1 * D + col) = o1;
                if (r2 < N) *reinterpret_cast<float2*>(outp + (size_t)r2 * D + col) = o2;
            }
        }
    }
}

// ---------------------------------------------------------------------------
extern "C" void kernel_launch(void* const* d_in, const int* in_sizes, int n_in,
                              void* d_out, int out_size) {
    const float* x   = (const float*)d_in[0];
    const void*  ei  = d_in[1];
    const float* Wl0 = (const float*)d_in[2];
    const float* bl0 = (const float*)d_in[3];
    const float* Wr0 = (const float*)d_in[4];
    const float* Wl1 = (const float*)d_in[5];
    const float* bl1 = (const float*)d_in[6];
    const float* Wr1 = (const float*)d_in[7];
    float*       out = (float*)d_out;

    int N = in_sizes[0] / D;
    int E = in_sizes[1] / 2;

    int n4           = N * (D / 4);
    int prep_blocks  = (n4 + 255) / 256;
    int edge4_blocks = ((E + 3) / 4 + 255) / 256;
    int scan_grid    = (N + SCAN_BLK - 1) / SCAN_BLK;
    int gemm_blocks  = (N + 127) / 128;

    cudaFuncSetAttribute(sage_fused,
                         cudaFuncAttributeMaxDynamicSharedMemorySize, SMEM_TOTAL);

    prep_kernel<<<prep_blocks, 256>>>((const long long*)ei, x,
                                      Wl0, Wr0, Wl1, Wr1, E, N, n4);
    count_kernel<<<edge4_blocks, 256>>>(ei, E, N);
    scan_kernel<<<scan_grid, SCAN_BLK>>>(N);
    fill_kernel<<<edge4_blocks, 256>>>(ei, E, N);

    sage_fused<<<gemm_blocks, 256, SMEM_TOTAL>>>(bl0, out, N, E, /*layer=*/0);
    sage_fused<<<gemm_blocks, 256, SMEM_TOTAL>>>(bl1, out, N, E, /*layer=*/1);
}

// round 14
// speedup vs baseline: 1.6010x; 1.6010x over previous
#include <cuda_runtime.h>
#include <cuda_fp16.h>
#include <cstdint>

#define D 128
#define MAXN 50000
#define NPAD 50176                 // padded rows so GEMM tail loads stay in-bounds
#define MAXE 800000
#define SCAN_BLK 512
#define SCAN_GRID ((MAXN + SCAN_BLK - 1) / SCAN_BLK)   // 98

// Scratch (device globals — no runtime allocation allowed)
__device__ __half g_x16[(size_t)NPAD * D];   // fp16 x (gather + GEMM A)
__device__ __half g_h16[(size_t)NPAD * D];   // fp16 h (gather + GEMM A)
__device__ __half g_a16[(size_t)NPAD * D];   // fp16 agg mean (GEMM A)
__device__ __half g_w16[2 * 128 * 256];      // fp16 W [layer][n][k] (k<128=Wl, else Wr)
__device__ int    g_deg[MAXN];               // counts -> exclusive prefix (in place)
__device__ int    g_part[SCAN_GRID];         // -> exclusive block offsets
__device__ int    g_slot[MAXE];              // per-edge within-node slot (from count)
__device__ int    g_perm[MAXE];
__device__ int    g_done;                    // scan completion counter (self-resetting)
__device__ int    g_idx64;

// ---------------------------------------------------------------------------
__device__ __forceinline__ uint32_t smem_u32(const void* p) {
    uint32_t a;
    asm("{ .reg .u64 t; cvta.to.shared.u64 t, %1; cvt.u32.u64 %0, t; }"
        : "=r"(a) : "l"(p));
    return a;
}
__device__ __forceinline__ void ldsm_x4(uint32_t& r0, uint32_t& r1,
                                        uint32_t& r2, uint32_t& r3, uint32_t addr) {
    asm volatile("ldmatrix.sync.aligned.m8n8.x4.shared.b16 {%0,%1,%2,%3}, [%4];"
                 : "=r"(r0), "=r"(r1), "=r"(r2), "=r"(r3) : "r"(addr));
}
__device__ __forceinline__ void mma_fp16(float* c, const uint32_t* a, const uint32_t* b) {
    asm volatile(
        "mma.sync.aligned.m16n8k16.row.col.f32.f16.f16.f32 "
        "{%0,%1,%2,%3}, {%4,%5,%6,%7}, {%8,%9}, {%0,%1,%2,%3};"
        : "+f"(c[0]), "+f"(c[1]), "+f"(c[2]), "+f"(c[3])
        : "r"(a[0]), "r"(a[1]), "r"(a[2]), "r"(a[3]), "r"(b[0]), "r"(b[1]));
}

__device__ __forceinline__ int clampN(long long v, int N) {
    if (v < 0) v = 0;
    if (v >= N) v = N - 1;
    return (int)v;
}

// ---------------------------------------------------------------------------
// Merged prep: zero deg + dtype detection + x->fp16 + W->fp16
// ---------------------------------------------------------------------------
__global__ void prep_kernel(const long long* __restrict__ e,
                            const float* __restrict__ x,
                            const float* __restrict__ Wl0, const float* __restrict__ Wr0,
                            const float* __restrict__ Wl1, const float* __restrict__ Wr1,
                            int E, int N, int n4) {
    int i = blockIdx.x * blockDim.x + threadIdx.x;

    if (i < N) g_deg[i] = 0;

    if (i < n4) {
        float4 v = reinterpret_cast<const float4*>(x)[i];
        __half2 p0 = __floats2half2_rn(v.x, v.y);
        __half2 p1 = __floats2half2_rn(v.z, v.w);
        uint2 pk;
        pk.x = *reinterpret_cast<uint32_t*>(&p0);
        pk.y = *reinterpret_cast<uint32_t*>(&p1);
        reinterpret_cast<uint2*>(g_x16)[i] = pk;
    }

    if (i < 2 * 128 * 256) {
        int layer = i >> 15;
        int rem   = i & 32767;
        int n     = rem >> 8;
        int k     = rem & 255;
        const float* W = layer ? (k < 128 ? Wl1 : Wr1) : (k < 128 ? Wl0 : Wr0);
        g_w16[i] = __float2half_rn(W[n * 128 + (k & 127)]);
    }

    if (blockIdx.x == 0) {
        __shared__ int bad;
        if (threadIdx.x == 0) bad = 0;
        __syncthreads();
        int limit = 1024 < 2 * E ? 1024 : 2 * E;
        for (int k = threadIdx.x; k < limit; k += blockDim.x) {
            long long v = e[k];
            if (v < 0 || v >= (long long)N) bad = 1;
        }
        __syncthreads();
        if (threadIdx.x == 0) g_idx64 = bad ? 0 : 1;
    }
}

// ---------------------------------------------------------------------------
// CSR build. count also records each edge's within-node slot (the atomic's
// return value), so fill needs no atomics at all.
// ---------------------------------------------------------------------------
__global__ void count_kernel(const void* __restrict__ eidx, int E, int N) {
    int t = blockIdx.x * blockDim.x + threadIdx.x;
    int e0 = t * 4;
    if (e0 >= E) return;
    int m = E - e0;
    int d[4];
    if (g_idx64) {
        const long long* ei = (const long long*)eidx + E;
#pragma unroll
        for (int j = 0; j < 4; j++) d[j] = clampN(ei[(j < m) ? e0 + j : e0], N);
    } else {
        const int* ei = (const int*)eidx + E;
        if (m >= 4) {
            int4 p = *reinterpret_cast<const int4*>(ei + e0);
            d[0] = clampN(p.x, N); d[1] = clampN(p.y, N);
            d[2] = clampN(p.z, N); d[3] = clampN(p.w, N);
        } else {
#pragma unroll
            for (int j = 0; j < 4; j++) d[j] = clampN(ei[(j < m) ? e0 + j : e0], N);
        }
    }
    int r[4];
#pragma unroll
    for (int j = 0; j < 4; j++)
        if (j < m) r[j] = atomicAdd(&g_deg[d[j]], 1);
    if (m >= 4) {
        *reinterpret_cast<int4*>(g_slot + e0) = make_int4(r[0], r[1], r[2], r[3]);
    } else {
#pragma unroll
        for (int j = 0; j < 4; j++)
            if (j < m) g_slot[e0 + j] = r[j];
    }
}

// Merged scan: per-block exclusive scan of deg; last-finishing block scans the
// block partials. rowptr[i] computed by consumers as deg[i] + part[i>>9].
__global__ void scan_kernel(int N) {
    __shared__ int sh[SCAN_BLK];
    __shared__ int isLast;
    int t = threadIdx.x;
    int i = blockIdx.x * SCAN_BLK + t;
    int v = (i < N) ? g_deg[i] : 0;
    sh[t] = v;
    __syncthreads();
#pragma unroll
    for (int ofs = 1; ofs < SCAN_BLK; ofs <<= 1) {
        int add = (t >= ofs) ? sh[t - ofs] : 0;
        __syncthreads();
        sh[t] += add;
        __syncthreads();
    }
    if (i < N) g_deg[i] = sh[t] - v;          // exclusive within block
    if (t == SCAN_BLK - 1) g_part[blockIdx.x] = sh[t];

    __threadfence();
    if (t == 0) isLast = (atomicAdd(&g_done, 1) == (int)gridDim.x - 1);
    __syncthreads();
    if (isLast) {
        int nb = gridDim.x;
        int pv = (t < nb) ? g_part[t] : 0;
        sh[t] = pv;
        __syncthreads();
#pragma unroll
        for (int ofs = 1; ofs < SCAN_BLK; ofs <<= 1) {
            int add = (t >= ofs) ? sh[t - ofs] : 0;
            __syncthreads();
            sh[t] += add;
            __syncthreads();
        }
        if (t < nb) g_part[t] = sh[t] - pv;   // exclusive block offsets
        if (t == 0) g_done = 0;               // reset for next graph replay
    }
}

// Atomic-free fill: pos = rowptr[d] + slot[e]
__global__ void fill_kernel(const void* __restrict__ eidx, int E, int N) {
    int t = blockIdx.x * blockDim.x + threadIdx.x;
    int e0 = t * 4;
    if (e0 >= E) return;
    int m = E - e0;
    int s[4], d[4], r[4];
    if (g_idx64) {
        const long long* es = (const long long*)eidx;
        const long long* ed = es + E;
#pragma unroll
        for (int j = 0; j < 4; j++) {
            int e = (j < m) ? e0 + j : e0;
            s[j] = clampN(es[e], N);
            d[j] = clampN(ed[e], N);
        }
    } else {
        const int* es = (const int*)eidx;
        const int* ed = es + E;
        if (m >= 4) {
            int4 ps = *reinterpret_cast<const int4*>(es + e0);
            int4 pd = *reinterpret_cast<const int4*>(ed + e0);
            s[0] = clampN(ps.x, N); s[1] = clampN(ps.y, N);
            s[2] = clampN(ps.z, N); s[3] = clampN(ps.w, N);
            d[0] = clampN(pd.x, N); d[1] = clampN(pd.y, N);
            d[2] = clampN(pd.z, N); d[3] = clampN(pd.w, N);
        } else {
#pragma unroll
            for (int j = 0; j < 4; j++) {
                int e = (j < m) ? e0 + j : e0;
                s[j] = clampN(es[e], N);
                d[j] = clampN(ed[e], N);
            }
        }
    }
    if (m >= 4) {
        int4 pr = *reinterpret_cast<const int4*>(g_slot + e0);
        r[0] = pr.x; r[1] = pr.y; r[2] = pr.z; r[3] = pr.w;
    } else {
#pragma unroll
        for (int j = 0; j < 4; j++)
            if (j < m) r[j] = g_slot[e0 + j];
    }
#pragma unroll
    for (int j = 0; j < 4; j++)
        if (j < m) {
            int dj = d[j];
            g_perm[g_deg[dj] + g_part[dj >> 9] + r[j]] = s[j];
        }
}

// ---------------------------------------------------------------------------
// Gather aggregation (fp16): one warp per dst node; mean written as fp16.
// rowptr computed inline from deg+part.
// ---------------------------------------------------------------------------
__global__ void __launch_bounds__(256)
agg_kernel(int N, int E, int use_h) {
    int gw = (blockIdx.x * blockDim.x + threadIdx.x) >> 5;
    int lane = threadIdx.x & 31;
    if (gw >= N) return;

    const __half* __restrict__ X = use_h ? g_h16 : g_x16;
    int beg = g_deg[gw] + g_part[gw >> 9];
    int end = (gw + 1 < N) ? (g_deg[gw + 1] + g_part[(gw + 1) >> 9]) : E;

    float a0 = 0.f, a1 = 0.f, a2 = 0.f, a3 = 0.f;
    for (int base = beg; base < end; base += 32) {
        int idx = base + lane;
        int sv = (idx < end) ? g_perm[idx] : 0;
        int m = min(32, end - base);
        for (int j = 0; j < m; j++) {
            int s = __shfl_sync(0xffffffffu, sv, j);
            uint2 pk = reinterpret_cast<const uint2*>(X + (size_t)s * D)[lane];
            __half2 h0 = *reinterpret_cast<__half2*>(&pk.x);
            __half2 h1 = *reinterpret_cast<__half2*>(&pk.y);
            float2 f0 = __half22float2(h0);
            float2 f1 = __half22float2(h1);
            a0 += f0.x; a1 += f0.y; a2 += f1.x; a3 += f1.y;
        }
    }
    float inv = (end > beg) ? 1.0f / (float)(end - beg) : 0.f;
    __half2 p0 = __floats2half2_rn(a0 * inv, a1 * inv);
    __half2 p1 = __floats2half2_rn(a2 * inv, a3 * inv);
    uint2 pk;
    pk.x = *reinterpret_cast<uint32_t*>(&p0);
    pk.y = *reinterpret_cast<uint32_t*>(&p1);
    reinterpret_cast<uint2*>(g_a16 + (size_t)gw * D)[lane] = pk;
}

// ---------------------------------------------------------------------------
// fp16 single-pass fused SAGE GEMM:  D = A * W  (A, W fp16; fp32 accum)
// 128x128 tile per CTA, K=256 in 4 chunks of 64.
// ---------------------------------------------------------------------------
#define ROWB 144
#define TILE_BYTES (128 * ROWB)
#define SA    0
#define SB    (SA + TILE_BYTES)
#define SMEM_TOTAL (2 * TILE_BYTES)   // 36864

__global__ void __launch_bounds__(256, 2)
sage_gemm_tc(const float* __restrict__ bias,
             float* __restrict__ outp,
             int N, int layer) {
    extern __shared__ __align__(128) char smem[];
    uint32_t sb = smem_u32(smem);

    int tid = threadIdx.x, wid = tid >> 5, lane = tid & 31;
    int warpM = wid & 3, warpN = wid >> 2;
    int row0 = blockIdx.x * 128;
    int relu = (layer == 0);

    uint32_t aoff[2], boff[4];
#pragma unroll
    for (int mi = 0; mi < 2; mi++)
        aoff[mi] = (uint32_t)((warpM * 32 + mi * 16 + (lane & 15)) * ROWB + (lane >> 4) * 16);
#pragma unroll
    for (int np = 0; np < 4; np++)
        boff[np] = (uint32_t)((warpN * 64 + np * 16 + (lane & 7) + ((lane & 16) ? 8 : 0)) * ROWB
                              + ((lane >> 3) & 1) * 16);

    float acc[2][8][4];
#pragma unroll
    for (int mi = 0; mi < 2; mi++)
#pragma unroll
        for (int ni = 0; ni < 8; ni++)
#pragma unroll
            for (int j = 0; j < 4; j++) acc[mi][ni][j] = 0.f;

    for (int c = 0; c < 4; c++) {
        const __half* __restrict__ A =
            (c < 2) ? g_a16 : (layer ? g_h16 : g_x16);
        const int kb = (c & 1) * 64;

        if (c > 0) __syncthreads();

#pragma unroll
        for (int i = 0; i < 4; i++) {
            int f = i * 256 + tid;    // uint4 index 0..1023
            int r = f >> 3;           // row 0..127
            int c8 = (f & 7) * 8;     // fp16 col offset 0..56
            int sm = r * ROWB + c8 * 2;

            *reinterpret_cast<uint4*>(smem + SA + sm) =
                *reinterpret_cast<const uint4*>(A + (size_t)(row0 + r) * D + kb + c8);

            size_t gb = ((size_t)layer * 128 + r) * 256 + c * 64 + c8;
            *reinterpret_cast<uint4*>(smem + SB + sm) =
                *reinterpret_cast<const uint4*>(g_w16 + gb);
        }
        __syncthreads();

#pragma unroll
        for (int ks = 0; ks < 4; ks++) {
            uint32_t kbyte = (uint32_t)(ks * 32);
            uint32_t a[2][4], b[8][2];
#pragma unroll
            for (int mi = 0; mi < 2; mi++)
                ldsm_x4(a[mi][0], a[mi][1], a[mi][2], a[mi][3],
                        sb + SA + aoff[mi] + kbyte);
#pragma unroll
            for (int np = 0; np < 4; np++)
                ldsm_x4(b[2 * np][0], b[2 * np][1], b[2 * np + 1][0], b[2 * np + 1][1],
                        sb + SB + boff[np] + kbyte);
#pragma unroll
            for (int mi = 0; mi < 2; mi++)
#pragma unroll
                for (int ni = 0; ni < 8; ni++)
                    mma_fp16(acc[mi][ni], a[mi], b[ni]);
        }
    }

    int g = lane >> 2, t = lane & 3;
#pragma unroll
    for (int mi = 0; mi < 2; mi++) {
        int r1 = row0 + warpM * 32 + mi * 16 + g;
        int r2 = r1 + 8;
#pragma unroll
        for (int ni = 0; ni < 8; ni++) {
            int col = warpN * 64 + ni * 8 + t * 2;
            float2 bs = *reinterpret_cast<const float2*>(bias + col);
            float2 o1, o2;
            o1.x = acc[mi][ni][0] + bs.x; o1.y = acc[mi][ni][1] + bs.y;
            o2.x = acc[mi][ni][2] + bs.x; o2.y = acc[mi][ni][3] + bs.y;
            if (relu) {
                o1.x = fmaxf(o1.x, 0.f); o1.y = fmaxf(o1.y, 0.f);
                o2.x = fmaxf(o2.x, 0.f); o2.y = fmaxf(o2.y, 0.f);
            }
            if (layer == 0) {
                if (r1 < N) {
                    __half2 p = __floats2half2_rn(o1.x, o1.y);
                    *reinterpret_cast<__half2*>(g_h16 + (size_t)r1 * D + col) = p;
                }
                if (r2 < N) {
                    __half2 p = __floats2half2_rn(o2.x, o2.y);
                    *reinterpret_cast<__half2*>(g_h16 + (size_t)r2 * D + col) = p;
                }
            } else {
                if (r1 < N) *reinterpret_cast<float2*>(outp + (size_t)r1 * D + col) = o1;
                if (r2 < N) *reinterpret_cast<float2*>(outp + (size_t)r2 * D + col) = o2;
            }
        }
    }
}

// ---------------------------------------------------------------------------
extern "C" void kernel_launch(void* const* d_in, const int* in_sizes, int n_in,
                              void* d_out, int out_size) {
    const float* x   = (const float*)d_in[0];
    const void*  ei  = d_in[1];
    const float* Wl0 = (const float*)d_in[2];
    const float* bl0 = (const float*)d_in[3];
    const float* Wr0 = (const float*)d_in[4];
    const float* Wl1 = (const float*)d_in[5];
    const float* bl1 = (const float*)d_in[6];
    const float* Wr1 = (const float*)d_in[7];
    float*       out = (float*)d_out;

    int N = in_sizes[0] / D;
    int E = in_sizes[1] / 2;

    int n4           = N * (D / 4);
    int prep_blocks  = (n4 + 255) / 256;
    int edge4_blocks = ((E + 3) / 4 + 255) / 256;
    int scan_grid    = (N + SCAN_BLK - 1) / SCAN_BLK;
    int agg_blocks   = (N * 32 + 255) / 256;
    int gemm_blocks  = (N + 127) / 128;

    cudaFuncSetAttribute(sage_gemm_tc,
                         cudaFuncAttributeMaxDynamicSharedMemorySize, SMEM_TOTAL);

    prep_kernel<<<prep_blocks, 256>>>((const long long*)ei, x,
                                      Wl0, Wr0, Wl1, Wr1, E, N, n4);
    count_kernel<<<edge4_blocks, 256>>>(ei, E, N);
    scan_kernel<<<scan_grid, SCAN_BLK>>>(N);
    fill_kernel<<<edge4_blocks, 256>>>(ei, E, N);

    // Layer 0
    agg_kernel<<<agg_blocks, 256>>>(N, E, /*use_h=*/0);
    sage_gemm_tc<<<gemm_blocks, 256, SMEM_TOTAL>>>(bl0, out, N, /*layer=*/0);
    // Layer 1
    agg_kernel<<<agg_blocks, 256>>>(N, E, /*use_h=*/1);
    sage_gemm_tc<<<gemm_blocks, 256, SMEM_TOTAL>>>(bl1, out, N, /*layer=*/1);
}